// round 16
// baseline (speedup 1.0000x reference)
#include <cuda_runtime.h>
#include <math.h>

// Problem constants
#define NXg 302
#define NYg 394
#define Bb  16
#define Dd  128
#define KK  16
#define UNITS 96
#define NP   197                // float2 column pairs per row
#define SPR  50                 // 8-pt strips per row (last strip = 2 pts)
#define WPBATCH (NXg * SPR)     // 15100 strips per batch
#define TPB 256
#define BPB ((WPBATCH + TPB - 1) / TPB)   // 59 blocks per batch

__device__ __forceinline__ float ex2a(float x) {
    float y; asm("ex2.approx.f32 %0, %1;" : "=f"(y) : "f"(x)); return y;
}

// ---------------------------------------------------------------------------
// Fused kernel, fully scalar eval, 8-point strips (high warp supply).
// Prologue: vectorized redundant GEMM (float4) + shuffle softmax + scalar
// per-component constants (NOT duplicated).
// Main: one thread = one 8-point strip x all 16 components. Per k: scalar
// setup + MUFU anchor + stride-1 geometric recurrence.
// ---------------------------------------------------------------------------
__global__ __launch_bounds__(TPB) void mdn_fused_kernel(
    const float* __restrict__ inp,
    const float* __restrict__ w,
    const float* __restrict__ bias,
    float* __restrict__ out)
{
    __shared__ float s_in[Dd];
    __shared__ float s_part[8][UNITS];
    __shared__ float s_y[UNITS];
    __shared__ float sp[KK * 12];   // scalar params, stride 12 (16B aligned)

    const int b = blockIdx.y;
    const int t = threadIdx.x;

    if (t < Dd) s_in[t] = inp[b * Dd + t];
    __syncthreads();

    // vectorized split GEMM: 192 threads; g = t%24 (units 4g..4g+3),
    // c = t/24 (depth 16c..16c+15); 16 LDG.128 + 64 FMA each
    if (t < 192) {
        const int g = t % 24;
        const int c = t / 24;
        const float* wc = w + (c * 16) * UNITS + 4 * g;
        const float* ic = s_in + c * 16;
        float4 acc = make_float4(0.f, 0.f, 0.f, 0.f);
#pragma unroll
        for (int dd = 0; dd < 16; ++dd) {
            const float4 wv = *reinterpret_cast<const float4*>(wc + dd * UNITS);
            const float xi = ic[dd];
            acc.x = fmaf(xi, wv.x, acc.x);
            acc.y = fmaf(xi, wv.y, acc.y);
            acc.z = fmaf(xi, wv.z, acc.z);
            acc.w = fmaf(xi, wv.w, acc.w);
        }
        *reinterpret_cast<float4*>(&s_part[c][4 * g]) = acc;
    }
    __syncthreads();

    if (t < UNITS) {
        float y = bias[t];
#pragma unroll
        for (int c = 0; c < 8; ++c) y += s_part[c][t];
        s_y[t] = y;
    }
    __syncthreads();

    if (t < KK) {
        const int k = t;
        const float LOG2E    = 1.4426950408889634f;
        const float LOG2_2PI = 2.6514961294723187f;
        const float K2E      = -0.7213475204444817f;   // -0.5*log2(e)

        const float mux = s_y[2 * k];
        const float muy = s_y[2 * k + 1];
        const float aa  = s_y[2 * KK + 3 * k];
        const float s22 = s_y[2 * KK + 3 * k + 1];
        const float s11 = s_y[2 * KK + 3 * k + 2];
        const float pik = s_y[5 * KK + k];

        // shuffle softmax stats across lanes 0..15
        float m = pik;
#pragma unroll
        for (int s = 1; s < KK; s <<= 1)
            m = fmaxf(m, __shfl_xor_sync(0x0000FFFFu, m, s));
        float S = ex2a((pik - m) * LOG2E);
#pragma unroll
        for (int s = 1; s < KK; s <<= 1)
            S += __shfl_xor_sync(0x0000FFFFu, S, s);
        float lg2S; asm("lg2.approx.f32 %0, %1;" : "=f"(lg2S) : "f"(S));

        const float A1 = ex2a(-s11 * LOG2E);   // 1/L11
        const float A2 = ex2a(-s22 * LOG2E);   // 1/L22
        const float LC = (pik - m - s11 - s22) * LOG2E - lg2S - LOG2_2PI;

        const float dyv = 1.0f / (NYg - 1);
        const float S1 = A2 * dyv;             // z2 step per +1 column
        const float G1 = 2.0f * K2E * S1;
        const float G0 = K2E * S1 * S1;
        const float cs = ex2a(G1 * S1);        // ratio of ratios (<1)

        float* P = &sp[k * 12];
        P[0] = A1;
        P[1] = -mux * A1;
        P[2] = A2;
        P[3] = -muy * A2;
        P[4] = -aa * A2;
        P[5] = LC;
        P[6] = G1;
        P[7] = G0;
        P[8] = cs;
        P[9] = 0.0f; P[10] = 0.0f; P[11] = 0.0f;
    }
    __syncthreads();

    // ---- main eval (scalar, 8-pt strip) ----
    const int wi = blockIdx.x * TPB + t;
    if (wi >= WPBATCH) return;     // safe: no syncs/shuffles below

    const int i     = wi / SPR;
    const int strip = wi - i * SPR;
    const int j0    = strip * 8;

    const float x  = (float)i * (1.0f / (NXg - 1));
    const float y0 = (float)j0 * (1.0f / (NYg - 1));
    const float K2E = -0.7213475204444817f;

    float acc[8];
#pragma unroll
    for (int n = 0; n < 8; ++n) acc[n] = 0.0f;

#pragma unroll
    for (int k = 0; k < KK; ++k) {
        const float4 pa = *reinterpret_cast<const float4*>(&sp[k * 12]);     // A1,B1,A2,B2
        const float4 pb = *reinterpret_cast<const float4*>(&sp[k * 12 + 4]); // C2,LC,G1,G0
        const float cs  = sp[k * 12 + 8];

        const float z1  = fmaf(x, pa.x, pa.y);
        const float z1s = z1 * z1;
        const float W   = fmaf(pb.x, z1, pa.w);
        const float z2  = fmaf(y0, pa.z, W);
        const float m   = fmaf(z2, z2, z1s);
        const float a0  = fmaf(m, K2E, pb.y);
        float E = ex2a(a0);                          // flushes to +0 far away
        const float dq = fmaf(z2, pb.z, pb.w);
        float r = ex2a(fminf(dq, 12.0f));            // cheap insurance clamp

        acc[0] += E;
#pragma unroll
        for (int n = 1; n < 8; ++n) {
            E *= r;
            if (n < 7) r *= cs;
            acc[n] += E;
        }
    }

    // store 4 float2 pairs (1 on the tail strip: 394 = 49*8 + 2)
    float2* o2 = reinterpret_cast<float2*>(out);
    const size_t base = (size_t)(b * NXg + i) * NP + strip * 4;
    const int npairs = min(4, NP - strip * 4);
#pragma unroll
    for (int n = 0; n < 4; ++n)
        if (n < npairs) o2[base + n] = make_float2(acc[2 * n], acc[2 * n + 1]);
}

// ---------------------------------------------------------------------------
extern "C" void kernel_launch(void* const* d_in, const int* in_sizes, int n_in,
                              void* d_out, int out_size)
{
    const float* inp  = (const float*)d_in[0];   // [16,128]
    const float* w    = (const float*)d_in[1];   // [128,96]
    const float* bias = (const float*)d_in[2];   // [96]
    float* out = (float*)d_out;                  // [16,302,394,1]

    dim3 grid(BPB, Bb);
    mdn_fused_kernel<<<grid, TPB>>>(inp, w, bias, out);
}

// round 17
// speedup vs baseline: 1.0443x; 1.0443x over previous
#include <cuda_runtime.h>
#include <math.h>

// Problem constants
#define NXg 302
#define NYg 394
#define Bb  16
#define Dd  128
#define KK  16
#define UNITS 96
#define NP   197                // float2 column pairs per row
#define SPR  25                 // 16-pt strips per row (last strip = 10 pts)
#define WPBATCH (NXg * SPR)     // 7550 strips per batch
#define TPB 256
#define BPB ((WPBATCH + TPB - 1) / TPB)   // 30 blocks per batch

__device__ __forceinline__ float ex2a(float x) {
    float y; asm("ex2.approx.f32 %0, %1;" : "=f"(y) : "f"(x)); return y;
}

// ---------------------------------------------------------------------------
// Fused kernel, fully scalar eval, 16-pt strips, 2-way k-interleaved ILP.
// Prologue: vectorized redundant GEMM (float4) + shuffle softmax + scalar
// per-component constants (NOT duplicated).
// Main: one thread = one 16-point strip x all 16 components, processed as
// 8 iterations each handling components k and k+8 with independent E/r
// recurrence chains (2x ILP on the FFMA critical path).
// ---------------------------------------------------------------------------
__global__ __launch_bounds__(TPB) void mdn_fused_kernel(
    const float* __restrict__ inp,
    const float* __restrict__ w,
    const float* __restrict__ bias,
    float* __restrict__ out)
{
    __shared__ float s_in[Dd];
    __shared__ float s_part[8][UNITS];
    __shared__ float s_y[UNITS];
    __shared__ float sp[KK * 12];   // scalar params, stride 12 (16B aligned)

    const int b = blockIdx.y;
    const int t = threadIdx.x;

    if (t < Dd) s_in[t] = inp[b * Dd + t];
    __syncthreads();

    // vectorized split GEMM: 192 threads; g = t%24 (units 4g..4g+3),
    // c = t/24 (depth 16c..16c+15); 16 LDG.128 + 64 FMA each
    if (t < 192) {
        const int g = t % 24;
        const int c = t / 24;
        const float* wc = w + (c * 16) * UNITS + 4 * g;
        const float* ic = s_in + c * 16;
        float4 acc = make_float4(0.f, 0.f, 0.f, 0.f);
#pragma unroll
        for (int dd = 0; dd < 16; ++dd) {
            const float4 wv = *reinterpret_cast<const float4*>(wc + dd * UNITS);
            const float xi = ic[dd];
            acc.x = fmaf(xi, wv.x, acc.x);
            acc.y = fmaf(xi, wv.y, acc.y);
            acc.z = fmaf(xi, wv.z, acc.z);
            acc.w = fmaf(xi, wv.w, acc.w);
        }
        *reinterpret_cast<float4*>(&s_part[c][4 * g]) = acc;
    }
    __syncthreads();

    if (t < UNITS) {
        float y = bias[t];
#pragma unroll
        for (int c = 0; c < 8; ++c) y += s_part[c][t];
        s_y[t] = y;
    }
    __syncthreads();

    if (t < KK) {
        const int k = t;
        const float LOG2E    = 1.4426950408889634f;
        const float LOG2_2PI = 2.6514961294723187f;
        const float K2E      = -0.7213475204444817f;   // -0.5*log2(e)

        const float mux = s_y[2 * k];
        const float muy = s_y[2 * k + 1];
        const float aa  = s_y[2 * KK + 3 * k];
        const float s22 = s_y[2 * KK + 3 * k + 1];
        const float s11 = s_y[2 * KK + 3 * k + 2];
        const float pik = s_y[5 * KK + k];

        // shuffle softmax stats across lanes 0..15
        float m = pik;
#pragma unroll
        for (int s = 1; s < KK; s <<= 1)
            m = fmaxf(m, __shfl_xor_sync(0x0000FFFFu, m, s));
        float S = ex2a((pik - m) * LOG2E);
#pragma unroll
        for (int s = 1; s < KK; s <<= 1)
            S += __shfl_xor_sync(0x0000FFFFu, S, s);
        float lg2S; asm("lg2.approx.f32 %0, %1;" : "=f"(lg2S) : "f"(S));

        const float A1 = ex2a(-s11 * LOG2E);   // 1/L11
        const float A2 = ex2a(-s22 * LOG2E);   // 1/L22
        const float LC = (pik - m - s11 - s22) * LOG2E - lg2S - LOG2_2PI;

        const float dyv = 1.0f / (NYg - 1);
        const float S1 = A2 * dyv;             // z2 step per +1 column
        const float G1 = 2.0f * K2E * S1;
        const float G0 = K2E * S1 * S1;
        const float cs = ex2a(G1 * S1);        // ratio of ratios (<1)

        float* P = &sp[k * 12];
        P[0] = A1;
        P[1] = -mux * A1;
        P[2] = A2;
        P[3] = -muy * A2;
        P[4] = -aa * A2;
        P[5] = LC;
        P[6] = G1;
        P[7] = G0;
        P[8] = cs;
        P[9] = 0.0f; P[10] = 0.0f; P[11] = 0.0f;
    }
    __syncthreads();

    // ---- main eval (scalar, 16-pt strip, 2-way k interleave) ----
    const int wi = blockIdx.x * TPB + t;
    if (wi >= WPBATCH) return;     // safe: no syncs/shuffles below

    const int i     = wi / SPR;
    const int strip = wi - i * SPR;
    const int j0    = strip * 16;

    const float x  = (float)i * (1.0f / (NXg - 1));
    const float y0 = (float)j0 * (1.0f / (NYg - 1));
    const float K2E = -0.7213475204444817f;

    float acc[16];
#pragma unroll
    for (int n = 0; n < 16; ++n) acc[n] = 0.0f;

#pragma unroll
    for (int kk = 0; kk < KK / 2; ++kk) {
        const int ka = kk;
        const int kb = kk + KK / 2;

        const float4 pa0 = *reinterpret_cast<const float4*>(&sp[ka * 12]);     // A1,B1,A2,B2
        const float4 pb0 = *reinterpret_cast<const float4*>(&sp[ka * 12 + 4]); // C2,LC,G1,G0
        const float cs0  = sp[ka * 12 + 8];
        const float4 pa1 = *reinterpret_cast<const float4*>(&sp[kb * 12]);
        const float4 pb1 = *reinterpret_cast<const float4*>(&sp[kb * 12 + 4]);
        const float cs1  = sp[kb * 12 + 8];

        // chain 0 setup
        const float z1a  = fmaf(x, pa0.x, pa0.y);
        const float z1sa = z1a * z1a;
        const float Wa   = fmaf(pb0.x, z1a, pa0.w);
        const float z2a  = fmaf(y0, pa0.z, Wa);
        const float ma   = fmaf(z2a, z2a, z1sa);
        float E0 = ex2a(fmaf(ma, K2E, pb0.y));
        float r0 = ex2a(fminf(fmaf(z2a, pb0.z, pb0.w), 12.0f));

        // chain 1 setup
        const float z1b  = fmaf(x, pa1.x, pa1.y);
        const float z1sb = z1b * z1b;
        const float Wb   = fmaf(pb1.x, z1b, pa1.w);
        const float z2b  = fmaf(y0, pa1.z, Wb);
        const float mb   = fmaf(z2b, z2b, z1sb);
        float E1 = ex2a(fmaf(mb, K2E, pb1.y));
        float r1 = ex2a(fminf(fmaf(z2b, pb1.z, pb1.w), 12.0f));

        acc[0] += E0;
        acc[0] += E1;
#pragma unroll
        for (int n = 1; n < 16; ++n) {
            E0 *= r0;
            E1 *= r1;
            if (n < 15) { r0 *= cs0; r1 *= cs1; }
            acc[n] += E0;
            acc[n] += E1;
        }
    }

    // store 8 float2 pairs (5 on the tail strip: 394 = 24*16 + 10)
    float2* o2 = reinterpret_cast<float2*>(out);
    const size_t base = (size_t)(b * NXg + i) * NP + strip * 8;
    const int npairs = min(8, NP - strip * 8);
#pragma unroll
    for (int n = 0; n < 8; ++n)
        if (n < npairs) o2[base + n] = make_float2(acc[2 * n], acc[2 * n + 1]);
}

// ---------------------------------------------------------------------------
extern "C" void kernel_launch(void* const* d_in, const int* in_sizes, int n_in,
                              void* d_out, int out_size)
{
    const float* inp  = (const float*)d_in[0];   // [16,128]
    const float* w    = (const float*)d_in[1];   // [128,96]
    const float* bias = (const float*)d_in[2];   // [96]
    float* out = (float*)d_out;                  // [16,302,394,1]

    dim3 grid(BPB, Bb);
    mdn_fused_kernel<<<grid, TPB>>>(inp, w, bias, out);
}